// round 1
// baseline (speedup 1.0000x reference)
#include <cuda_runtime.h>

// Problem dims (fixed for this problem instance)
#define B_   16
#define CIN  32
#define COUT 64
#define H_   16
#define W_   512
#define LRELU_SLOPE 0.3f
#define BN_EPS 1e-5f

// SMEM layout (float offsets)
// sQ / sK / sV / sPE : 16x512 each
#define SQ_OFF    0
#define SK_OFF    8192
#define SV_OFF    16384
#define SPE_OFF   24576
// scratch: union of conv x-staging (8ci x 4h x 520 = 16640) and S block (32x512 = 16384)
#define SCR_OFF   32768
#define SW_OFF    (SCR_OFF + 16640)   // 49408 : 4 tensors x 160 weights (BN-folded)
#define SBIAS_OFF (SW_OFF + 640)      // 50048 : 4 biases (+pad)
#define SRINV_OFF (SBIAS_OFF + 8)     // 50056 : 32 row 1/sum values
#define SMEM_FLOATS (SRINV_OFF + 32)  // 50088
#define SMEM_BYTES (SMEM_FLOATS * 4)  // 200352 bytes

#define XROW 520   // staged x row stride (data at idx 4+w, halos at 2,3,516,517)

__global__ __launch_bounds__(256, 1)
void conv_attn_fused_kernel(
    const float* __restrict__ x,
    const float* __restrict__ wq, const float* __restrict__ gq, const float* __restrict__ bq, const float* __restrict__ mq, const float* __restrict__ vq,
    const float* __restrict__ wk, const float* __restrict__ gk, const float* __restrict__ bk, const float* __restrict__ mk, const float* __restrict__ vk,
    const float* __restrict__ wv, const float* __restrict__ gv, const float* __restrict__ bv, const float* __restrict__ mv, const float* __restrict__ vv,
    const float* __restrict__ wp, const float* __restrict__ gp, const float* __restrict__ bp, const float* __restrict__ mp, const float* __restrict__ vp,
    float* __restrict__ out)
{
    extern __shared__ float sm[];
    const int bid = blockIdx.x;            // b*64 + c
    const int b   = bid >> 6;
    const int c   = bid & 63;
    const int tid = threadIdx.x;

    // ---------------- Load BN-folded conv weights ----------------
    // eff_w = w * gamma*rsqrt(var+eps); eff_b = beta - mean*scale
    if (tid < 160) {
        float sq = gq[c] * rsqrtf(vq[c] + BN_EPS);
        float sk = gk[c] * rsqrtf(vk[c] + BN_EPS);
        float sv = gv[c] * rsqrtf(vv[c] + BN_EPS);
        float sp = gp[c] * rsqrtf(vp[c] + BN_EPS);
        sm[SW_OFF + 0*160 + tid] = wq[c*160 + tid] * sq;
        sm[SW_OFF + 1*160 + tid] = wk[c*160 + tid] * sk;
        sm[SW_OFF + 2*160 + tid] = wv[c*160 + tid] * sv;
        sm[SW_OFF + 3*160 + tid] = wp[c*160 + tid] * sp;
    }
    if (tid == 0) {
        float sq = gq[c] * rsqrtf(vq[c] + BN_EPS);
        float sk = gk[c] * rsqrtf(vk[c] + BN_EPS);
        float sv = gv[c] * rsqrtf(vv[c] + BN_EPS);
        float sp = gp[c] * rsqrtf(vp[c] + BN_EPS);
        sm[SBIAS_OFF + 0] = bq[c] - mq[c] * sq;
        sm[SBIAS_OFF + 1] = bk[c] - mk[c] * sk;
        sm[SBIAS_OFF + 2] = bv[c] - mv[c] * sv;
        sm[SBIAS_OFF + 3] = bp[c] - mp[c] * sp;
    }
    // zero x-staging halos once (staging never overwrites them: writes idx [4, 516))
    if (tid < 128) {
        int row = tid >> 2;
        int q4  = tid & 3;
        int off = (q4 < 2) ? (2 + q4) : (514 + q4);  // {2,3,516,517}
        sm[SCR_OFF + row * XROW + off] = 0.0f;
    }

    // ---------------- Fused conv(1x5)+BN+LeakyReLU ----------------
    // thread -> (hgrp in 0..3, 8 consecutive w outputs)
    const int hgrp = tid >> 6;        // 0..3
    const int w0   = (tid & 63) << 3; // 0..504 step 8
    const float* xb = x + (size_t)b * CIN * H_ * W_;

    for (int hb = 0; hb < 4; hb++) {
        float acc[4][8];
        #pragma unroll
        for (int t = 0; t < 4; t++)
            #pragma unroll
            for (int j = 0; j < 8; j++) acc[t][j] = 0.0f;

        for (int cib = 0; cib < 4; cib++) {
            __syncthreads();   // protect scratch reuse (and first-iter weight/halo writes)
            // stage x[b, cib*8 .. +8, hb*4 .. +4, :] into scratch (float4 coalesced)
            for (int i = tid; i < 4096; i += 256) {
                int ci  = i >> 9;          // 0..7
                int rem = i & 511;
                int hh  = rem >> 7;        // 0..3
                int w4  = (rem & 127) << 2;
                float4 val = *(const float4*)&xb[(((size_t)(cib*8 + ci)) * H_ + (hb*4 + hh)) * W_ + w4];
                *(float4*)&sm[SCR_OFF + (ci*4 + hh) * XROW + 4 + w4] = val;
            }
            __syncthreads();

            #pragma unroll 2
            for (int ci = 0; ci < 8; ci++) {
                const float* xr = &sm[SCR_OFF + (ci*4 + hgrp) * XROW + w0];
                float4 x0 = *(const float4*)(xr);
                float4 x1 = *(const float4*)(xr + 4);
                float4 x2 = *(const float4*)(xr + 8);
                float4 x3 = *(const float4*)(xr + 12);
                float xv[16] = {x0.x,x0.y,x0.z,x0.w, x1.x,x1.y,x1.z,x1.w,
                                x2.x,x2.y,x2.z,x2.w, x3.x,x3.y,x3.z,x3.w};
                const int wbase = ((cib << 3) + ci) * 5;
                #pragma unroll
                for (int t = 0; t < 4; t++) {
                    const float* wr = &sm[SW_OFF + t*160 + wbase];
                    float g0 = wr[0], g1 = wr[1], g2 = wr[2], g3 = wr[3], g4 = wr[4];
                    #pragma unroll
                    for (int j = 0; j < 8; j++) {
                        float a = acc[t][j];
                        a = fmaf(xv[j+2], g0, a);
                        a = fmaf(xv[j+3], g1, a);
                        a = fmaf(xv[j+4], g2, a);
                        a = fmaf(xv[j+5], g3, a);
                        a = fmaf(xv[j+6], g4, a);
                        acc[t][j] = a;
                    }
                }
            }
        }
        // write q,k,v,pe rows (each thread owns exclusive (h, w0..w0+7))
        const int h = (hb << 2) + hgrp;
        float* dsts[4] = { sm + SQ_OFF, sm + SK_OFF, sm + SV_OFF, sm + SPE_OFF };
        #pragma unroll
        for (int t = 0; t < 4; t++) {
            float bias = sm[SBIAS_OFF + t];
            float y[8];
            #pragma unroll
            for (int j = 0; j < 8; j++) {
                float v_ = acc[t][j] + bias;
                y[j] = (v_ >= 0.0f) ? v_ : LRELU_SLOPE * v_;
            }
            float* d = dsts[t] + h * W_ + w0;
            *(float4*)(d)     = make_float4(y[0], y[1], y[2], y[3]);
            *(float4*)(d + 4) = make_float4(y[4], y[5], y[6], y[7]);
        }
    }
    __syncthreads();  // Q/K/V/PE complete, scratch free

    // ---------------- Attention: blockwise S = Q^T K, softmax, out += V*A ----
    const int tr  = tid >> 6;          // 0..3 : S row-group / out h-group
    const int tcb = (tid & 63) << 3;   // col base (8 cols)
    float oacc[4][8];                  // out rows {tr, tr+4, tr+8, tr+12}, cols tcb..+7
    #pragma unroll
    for (int i = 0; i < 4; i++)
        #pragma unroll
        for (int j = 0; j < 8; j++) oacc[i][j] = 0.0f;

    float* sS = sm + SCR_OFF;

    for (int wb = 0; wb < W_; wb += 32) {
        // --- S block: rows r=0..31 (w = wb+r), cols 0..511; thread tile 8x8
        float sacc[8][8];
        #pragma unroll
        for (int i = 0; i < 8; i++)
            #pragma unroll
            for (int j = 0; j < 8; j++) sacc[i][j] = 0.0f;

        #pragma unroll 2
        for (int h = 0; h < H_; h++) {
            const float* qr = sm + SQ_OFF + h * W_ + wb + (tr << 3);
            float4 q0 = *(const float4*)qr;
            float4 q1 = *(const float4*)(qr + 4);
            const float* kr = sm + SK_OFF + h * W_ + tcb;
            float4 k0 = *(const float4*)kr;
            float4 k1 = *(const float4*)(kr + 4);
            float qv[8] = {q0.x,q0.y,q0.z,q0.w,q1.x,q1.y,q1.z,q1.w};
            float kv[8] = {k0.x,k0.y,k0.z,k0.w,k1.x,k1.y,k1.z,k1.w};
            #pragma unroll
            for (int i = 0; i < 8; i++)
                #pragma unroll
                for (int j = 0; j < 8; j++)
                    sacc[i][j] = fmaf(qv[i], kv[j], sacc[i][j]);
        }
        __syncthreads();   // prior block's A reads done before overwrite
        #pragma unroll
        for (int i = 0; i < 8; i++) {
            float* sr = sS + ((tr << 3) + i) * W_ + tcb;
            *(float4*)(sr)     = make_float4(sacc[i][0], sacc[i][1], sacc[i][2], sacc[i][3]);
            *(float4*)(sr + 4) = make_float4(sacc[i][4], sacc[i][5], sacc[i][6], sacc[i][7]);
        }
        __syncthreads();

        // --- rowwise softmax (exp in place, 1/sum -> sRinv); warp owns 4 rows
        {
            const int warp = tid >> 5, lane = tid & 31;
            #pragma unroll
            for (int rr = 0; rr < 4; rr++) {
                const int r = (warp << 2) + rr;
                float* row = sS + r * W_;
                float m = -1e30f;
                #pragma unroll 16
                for (int j = lane; j < W_; j += 32) m = fmaxf(m, row[j]);
                #pragma unroll
                for (int o = 16; o; o >>= 1) m = fmaxf(m, __shfl_xor_sync(0xffffffffu, m, o));
                float s = 0.0f;
                #pragma unroll 16
                for (int j = lane; j < W_; j += 32) {
                    float e = __expf(row[j] - m);
                    row[j] = e;
                    s += e;
                }
                #pragma unroll
                for (int o = 16; o; o >>= 1) s += __shfl_xor_sync(0xffffffffu, s, o);
                if (lane == 0) sm[SRINV_OFF + r] = 1.0f / s;
            }
        }
        __syncthreads();

        // --- out update: oacc[h][v] += sum_r V[h][wb+r] * A[r][v] / rowsum(r)
        #pragma unroll 4
        for (int r = 0; r < 32; r++) {
            float rinv = sm[SRINV_OFF + r];
            float vr0 = sm[SV_OFF + (tr     ) * W_ + wb + r] * rinv;
            float vr1 = sm[SV_OFF + (tr + 4 ) * W_ + wb + r] * rinv;
            float vr2 = sm[SV_OFF + (tr + 8 ) * W_ + wb + r] * rinv;
            float vr3 = sm[SV_OFF + (tr + 12) * W_ + wb + r] * rinv;
            const float* ar = sS + r * W_ + tcb;
            float4 a0 = *(const float4*)ar;
            float4 a1 = *(const float4*)(ar + 4);
            float av[8] = {a0.x,a0.y,a0.z,a0.w,a1.x,a1.y,a1.z,a1.w};
            #pragma unroll
            for (int j = 0; j < 8; j++) {
                oacc[0][j] = fmaf(vr0, av[j], oacc[0][j]);
                oacc[1][j] = fmaf(vr1, av[j], oacc[1][j]);
                oacc[2][j] = fmaf(vr2, av[j], oacc[2][j]);
                oacc[3][j] = fmaf(vr3, av[j], oacc[3][j]);
            }
        }
    }

    // ---------------- epilogue: out = oacc + PE ----------------
    float* og = out + (size_t)bid * (H_ * W_);
    #pragma unroll
    for (int i = 0; i < 4; i++) {
        const int h = tr + (i << 2);
        const float* pe = sm + SPE_OFF + h * W_ + tcb;
        float4 p0 = *(const float4*)pe;
        float4 p1 = *(const float4*)(pe + 4);
        float* d = og + h * W_ + tcb;
        *(float4*)(d)     = make_float4(oacc[i][0] + p0.x, oacc[i][1] + p0.y,
                                        oacc[i][2] + p0.z, oacc[i][3] + p0.w);
        *(float4*)(d + 4) = make_float4(oacc[i][4] + p1.x, oacc[i][5] + p1.y,
                                        oacc[i][6] + p1.z, oacc[i][7] + p1.w);
    }
}

extern "C" void kernel_launch(void* const* d_in, const int* in_sizes, int n_in,
                              void* d_out, int out_size)
{
    cudaFuncSetAttribute(conv_attn_fused_kernel,
                         cudaFuncAttributeMaxDynamicSharedMemorySize, SMEM_BYTES);

    const float* x  = (const float*)d_in[0];
    const float* wq = (const float*)d_in[1];
    const float* gq = (const float*)d_in[2];
    const float* bq = (const float*)d_in[3];
    const float* mq = (const float*)d_in[4];
    const float* vq = (const float*)d_in[5];
    const float* wk = (const float*)d_in[6];
    const float* gk = (const float*)d_in[7];
    const float* bk = (const float*)d_in[8];
    const float* mk = (const float*)d_in[9];
    const float* vk = (const float*)d_in[10];
    const float* wv = (const float*)d_in[11];
    const float* gv = (const float*)d_in[12];
    const float* bv = (const float*)d_in[13];
    const float* mv = (const float*)d_in[14];
    const float* vv = (const float*)d_in[15];
    const float* wp = (const float*)d_in[16];
    const float* gp = (const float*)d_in[17];
    const float* bp = (const float*)d_in[18];
    const float* mp = (const float*)d_in[19];
    const float* vp = (const float*)d_in[20];

    conv_attn_fused_kernel<<<B_ * COUT, 256, SMEM_BYTES>>>(
        x,
        wq, gq, bq, mq, vq,
        wk, gk, bk, mk, vk,
        wv, gv, bv, mv, vv,
        wp, gp, bp, mp, vp,
        (float*)d_out);
}

// round 2
// speedup vs baseline: 1.1482x; 1.1482x over previous
#include <cuda_runtime.h>

// Problem dims (fixed)
#define B_   16
#define CIN  32
#define COUT 64
#define H_   16
#define W_   512
#define LRELU_SLOPE 0.3f
#define BN_EPS 1e-5f

typedef unsigned long long u64;

// ---- packed f32x2 helpers (sm_103a FFMA2 path, PTX-only) ----
__device__ __forceinline__ u64 pk2(float lo, float hi) {
    u64 r; asm("mov.b64 %0,{%1,%2};" : "=l"(r) : "f"(lo), "f"(hi)); return r;
}
__device__ __forceinline__ u64 dup2(float v) {
    u64 r; asm("mov.b64 %0,{%1,%1};" : "=l"(r) : "f"(v)); return r;
}
__device__ __forceinline__ void fma2(u64 &d, u64 a, u64 b) {
    asm("fma.rn.f32x2 %0,%1,%2,%0;" : "+l"(d) : "l"(a), "l"(b));
}
__device__ __forceinline__ void upk(u64 v, float &lo, float &hi) {
    asm("mov.b64 {%0,%1},%2;" : "=f"(lo), "=f"(hi) : "l"(v));
}

// ---- SMEM layout (float offsets) ----
#define SQ_OFF    0                    // 16x512
#define SK_OFF    8192
#define SV_OFF    16384
#define SPE_OFF   24576
#define SCR_OFF   32768                // union: conv staging 8ci x 4h x 520 = 16640 | S block 32x512 = 16384
#define SVN_OFF   (SCR_OFF + 16640)    // 49408 : VnT 32 x 20 (V^T * rinv, padded stride)
#define SW_OFF    (SVN_OFF + 640)      // 50048 : 4 tensors x 160 weights, duplicated (float2) = 1280
#define SBIAS_OFF (SW_OFF + 1280)      // 51328 : 4 biases (+pad)
#define SMEM_FLOATS (SBIAS_OFF + 8)    // 51336
#define SMEM_BYTES  (SMEM_FLOATS * 4)  // 205344 B

#define XROW  520   // staged x row stride: data at 4+w, zero halos at 2,3,516,517
#define VNROW 20

__global__ __launch_bounds__(512, 1)
void conv_attn_fused_kernel(
    const float* __restrict__ x,
    const float* __restrict__ wq, const float* __restrict__ gq, const float* __restrict__ bq, const float* __restrict__ mq, const float* __restrict__ vq,
    const float* __restrict__ wk, const float* __restrict__ gk, const float* __restrict__ bk, const float* __restrict__ mk, const float* __restrict__ vk,
    const float* __restrict__ wv, const float* __restrict__ gv, const float* __restrict__ bv, const float* __restrict__ mv, const float* __restrict__ vv,
    const float* __restrict__ wp, const float* __restrict__ gp, const float* __restrict__ bp, const float* __restrict__ mp, const float* __restrict__ vp,
    float* __restrict__ out)
{
    extern __shared__ float sm[];
    const int bid = blockIdx.x;            // b*64 + c
    const int b   = bid >> 6;
    const int c   = bid & 63;
    const int tid = threadIdx.x;

    // ---------------- BN-folded, DUPLICATED conv weights ----------------
    if (tid < 160) {
        float sq = gq[c] * rsqrtf(vq[c] + BN_EPS);
        float sk = gk[c] * rsqrtf(vk[c] + BN_EPS);
        float sv = gv[c] * rsqrtf(vv[c] + BN_EPS);
        float sp = gp[c] * rsqrtf(vp[c] + BN_EPS);
        float a;
        a = wq[c*160 + tid] * sq; sm[SW_OFF + 0*320 + 2*tid] = a; sm[SW_OFF + 0*320 + 2*tid + 1] = a;
        a = wk[c*160 + tid] * sk; sm[SW_OFF + 1*320 + 2*tid] = a; sm[SW_OFF + 1*320 + 2*tid + 1] = a;
        a = wv[c*160 + tid] * sv; sm[SW_OFF + 2*320 + 2*tid] = a; sm[SW_OFF + 2*320 + 2*tid + 1] = a;
        a = wp[c*160 + tid] * sp; sm[SW_OFF + 3*320 + 2*tid] = a; sm[SW_OFF + 3*320 + 2*tid + 1] = a;
    }
    if (tid == 0) {
        float sq = gq[c] * rsqrtf(vq[c] + BN_EPS);
        float sk = gk[c] * rsqrtf(vk[c] + BN_EPS);
        float sv = gv[c] * rsqrtf(vv[c] + BN_EPS);
        float sp = gp[c] * rsqrtf(vp[c] + BN_EPS);
        sm[SBIAS_OFF + 0] = bq[c] - mq[c] * sq;
        sm[SBIAS_OFF + 1] = bk[c] - mk[c] * sk;
        sm[SBIAS_OFF + 2] = bv[c] - mv[c] * sv;
        sm[SBIAS_OFF + 3] = bp[c] - mp[c] * sp;
    }
    // zero halos once (staging writes only [4,516))
    if (tid < 128) {
        int row = tid >> 2;
        int q4  = tid & 3;
        int off = (q4 < 2) ? (2 + q4) : (514 + q4);
        sm[SCR_OFF + row * XROW + off] = 0.0f;
    }

    // ---------------- Fused conv(1x5)+BN+LeakyReLU ----------------
    // 512 threads: hgrp = tid>>7 (h within 4-row block), 4 consecutive w per thread
    const int hgrp = tid >> 7;
    const int w0   = (tid & 127) << 2;
    const float* xb = x + (size_t)b * CIN * H_ * W_;

    for (int hb = 0; hb < 4; hb++) {
        u64 acc2[4][2];
        #pragma unroll
        for (int t = 0; t < 4; t++) { acc2[t][0] = 0ull; acc2[t][1] = 0ull; }

        for (int cib = 0; cib < 4; cib++) {
            // software-pipelined staging: LDG into regs before the barrier
            float4 stg[8];
            #pragma unroll
            for (int it = 0; it < 8; it++) {
                int i  = tid + (it << 9);
                int ci = i >> 9;
                int hh = (i >> 7) & 3;
                int w4 = (i & 127) << 2;
                stg[it] = *(const float4*)&xb[(((size_t)(cib*8 + ci)) * H_ + (hb*4 + hh)) * W_ + w4];
            }
            __syncthreads();   // prior scratch consumers done (also 1st-iter weight/halo writes)
            #pragma unroll
            for (int it = 0; it < 8; it++) {
                int i  = tid + (it << 9);
                int ci = i >> 9;
                int hh = (i >> 7) & 3;
                int w4 = (i & 127) << 2;
                *(float4*)&sm[SCR_OFF + (ci*4 + hh) * XROW + 4 + w4] = stg[it];
            }
            __syncthreads();

            #pragma unroll 2
            for (int ci = 0; ci < 8; ci++) {
                const float* xr = &sm[SCR_OFF + (ci*4 + hgrp) * XROW + w0];
                float4 x0 = *(const float4*)(xr);
                float4 x1 = *(const float4*)(xr + 4);
                float4 x2 = *(const float4*)(xr + 8);
                // xv[i] = staged[w0+2+i]; out j = sum_k w[k]*xv[j+k]
                u64 P[7];
                P[0] = pk2(x0.z, x0.w); P[1] = pk2(x0.w, x1.x);
                P[2] = pk2(x1.x, x1.y); P[3] = pk2(x1.y, x1.z);
                P[4] = pk2(x1.z, x1.w); P[5] = pk2(x1.w, x2.x);
                P[6] = pk2(x2.x, x2.y);
                const int wb2 = ((cib << 3) + ci) * 10;
                #pragma unroll
                for (int t = 0; t < 4; t++) {
                    const float* wr = &sm[SW_OFF + t*320 + wb2];
                    #pragma unroll
                    for (int k = 0; k < 5; k++) {
                        u64 wd = *(const u64*)(wr + 2*k);   // duplicated weight (broadcast LDS.64)
                        fma2(acc2[t][0], P[k],     wd);     // outputs (j0,j1)
                        fma2(acc2[t][1], P[k + 2], wd);     // outputs (j2,j3)
                    }
                }
            }
        }
        const int h = (hb << 2) + hgrp;
        float* dsts[4] = { sm + SQ_OFF, sm + SK_OFF, sm + SV_OFF, sm + SPE_OFF };
        #pragma unroll
        for (int t = 0; t < 4; t++) {
            float bias = sm[SBIAS_OFF + t];
            float y0, y1, y2, y3;
            upk(acc2[t][0], y0, y1); upk(acc2[t][1], y2, y3);
            y0 += bias; y1 += bias; y2 += bias; y3 += bias;
            y0 = (y0 >= 0.f) ? y0 : LRELU_SLOPE * y0;
            y1 = (y1 >= 0.f) ? y1 : LRELU_SLOPE * y1;
            y2 = (y2 >= 0.f) ? y2 : LRELU_SLOPE * y2;
            y3 = (y3 >= 0.f) ? y3 : LRELU_SLOPE * y3;
            *(float4*)&dsts[t][h * W_ + w0] = make_float4(y0, y1, y2, y3);
        }
    }
    __syncthreads();   // Q/K/V/PE ready for attention

    // ---------------- Attention ----------------
    const int rgrp = hgrp;           // tid>>7 : S row-group / out h-group
    const int cb   = w0;             // 4 columns per thread
    const int warp = tid >> 5, lane = tid & 31;
    u64 oacc2[4][2];                 // out rows rgrp*4..+3, cols cb..cb+3
    #pragma unroll
    for (int i = 0; i < 4; i++) { oacc2[i][0] = 0ull; oacc2[i][1] = 0ull; }

    float* sS = sm + SCR_OFF;

    #pragma unroll 1
    for (int wb = 0; wb < W_; wb += 32) {
        // --- S block: rows wb..wb+31 x all 512 cols; thread tile 8r x 4c
        u64 sacc2[8][2];
        #pragma unroll
        for (int i = 0; i < 8; i++) { sacc2[i][0] = 0ull; sacc2[i][1] = 0ull; }

        #pragma unroll 4
        for (int h = 0; h < H_; h++) {
            const float* qr = sm + SQ_OFF + h * W_ + wb + (rgrp << 3);
            float4 q0 = *(const float4*)qr;
            float4 q1 = *(const float4*)(qr + 4);
            float4 kv = *(const float4*)(sm + SK_OFF + h * W_ + cb);
            u64 Pk0 = pk2(kv.x, kv.y), Pk1 = pk2(kv.z, kv.w);
            float qs[8] = {q0.x, q0.y, q0.z, q0.w, q1.x, q1.y, q1.z, q1.w};
            #pragma unroll
            for (int i = 0; i < 8; i++) {
                u64 dq = dup2(qs[i]);
                fma2(sacc2[i][0], Pk0, dq);
                fma2(sacc2[i][1], Pk1, dq);
            }
        }
        __syncthreads();   // prior block's sS/VnT consumers done
        #pragma unroll
        for (int i = 0; i < 8; i++) {
            float a0, a1, a2, a3;
            upk(sacc2[i][0], a0, a1); upk(sacc2[i][1], a2, a3);
            *(float4*)&sS[((rgrp << 3) + i) * W_ + cb] = make_float4(a0, a1, a2, a3);
        }
        __syncthreads();

        // --- rowwise softmax (values register-resident between passes); warp owns 2 rows
        float rinv0, rinv1;
        #pragma unroll
        for (int rr = 0; rr < 2; rr++) {
            float* row = sS + (warp * 2 + rr) * W_;
            float e[16];
            #pragma unroll
            for (int k2 = 0; k2 < 16; k2++) e[k2] = row[lane + (k2 << 5)];
            float m = e[0];
            #pragma unroll
            for (int k2 = 1; k2 < 16; k2++) m = fmaxf(m, e[k2]);
            #pragma unroll
            for (int o = 16; o; o >>= 1) m = fmaxf(m, __shfl_xor_sync(0xffffffffu, m, o));
            float s = 0.0f;
            #pragma unroll
            for (int k2 = 0; k2 < 16; k2++) {
                float ev = __expf(e[k2] - m);
                s += ev;
                row[lane + (k2 << 5)] = ev;
            }
            #pragma unroll
            for (int o = 16; o; o >>= 1) s += __shfl_xor_sync(0xffffffffu, s, o);
            float ri = 1.0f / s;
            if (rr == 0) rinv0 = ri; else rinv1 = ri;
        }
        // VnT[r][h] = V[h][wb+r] * rinv[r]  (one write per lane)
        {
            int hh  = lane & 15;
            int rr2 = lane >> 4;
            int r   = warp * 2 + rr2;
            float rv = rr2 ? rinv1 : rinv0;
            sm[SVN_OFF + r * VNROW + hh] = sm[SV_OFF + hh * W_ + wb + r] * rv;
        }
        __syncthreads();

        // --- out update: oacc[h][c] += Vn[h][r] * A[r][c]
        #pragma unroll 4
        for (int r = 0; r < 32; r++) {
            float4 a4 = *(const float4*)&sS[r * W_ + cb];
            float4 vn = *(const float4*)&sm[SVN_OFF + r * VNROW + (rgrp << 2)];
            u64 Pa0 = pk2(a4.x, a4.y), Pa1 = pk2(a4.z, a4.w);
            u64 d0 = dup2(vn.x), d1 = dup2(vn.y), d2 = dup2(vn.z), d3 = dup2(vn.w);
            fma2(oacc2[0][0], Pa0, d0); fma2(oacc2[0][1], Pa1, d0);
            fma2(oacc2[1][0], Pa0, d1); fma2(oacc2[1][1], Pa1, d1);
            fma2(oacc2[2][0], Pa0, d2); fma2(oacc2[2][1], Pa1, d2);
            fma2(oacc2[3][0], Pa0, d3); fma2(oacc2[3][1], Pa1, d3);
        }
    }

    // ---------------- epilogue: out = oacc + PE ----------------
    float* og = out + (size_t)bid * (H_ * W_);
    #pragma unroll
    for (int i = 0; i < 4; i++) {
        const int h = (rgrp << 2) + i;
        float o0, o1, o2, o3;
        upk(oacc2[i][0], o0, o1); upk(oacc2[i][1], o2, o3);
        float4 pe = *(const float4*)&sm[SPE_OFF + h * W_ + cb];
        *(float4*)&og[h * W_ + cb] = make_float4(o0 + pe.x, o1 + pe.y, o2 + pe.z, o3 + pe.w);
    }
}

extern "C" void kernel_launch(void* const* d_in, const int* in_sizes, int n_in,
                              void* d_out, int out_size)
{
    cudaFuncSetAttribute(conv_attn_fused_kernel,
                         cudaFuncAttributeMaxDynamicSharedMemorySize, SMEM_BYTES);

    const float* x  = (const float*)d_in[0];
    const float* wq = (const float*)d_in[1];
    const float* gq = (const float*)d_in[2];
    const float* bq = (const float*)d_in[3];
    const float* mq = (const float*)d_in[4];
    const float* vq = (const float*)d_in[5];
    const float* wk = (const float*)d_in[6];
    const float* gk = (const float*)d_in[7];
    const float* bk = (const float*)d_in[8];
    const float* mk = (const float*)d_in[9];
    const float* vk = (const float*)d_in[10];
    const float* wv = (const float*)d_in[11];
    const float* gv = (const float*)d_in[12];
    const float* bv = (const float*)d_in[13];
    const float* mv = (const float*)d_in[14];
    const float* vv = (const float*)d_in[15];
    const float* wp = (const float*)d_in[16];
    const float* gp = (const float*)d_in[17];
    const float* bp = (const float*)d_in[18];
    const float* mp = (const float*)d_in[19];
    const float* vp = (const float*)d_in[20];

    conv_attn_fused_kernel<<<B_ * COUT, 512, SMEM_BYTES>>>(
        x,
        wq, gq, bq, mq, vq,
        wk, gk, bk, mk, vk,
        wv, gv, bv, mv, vv,
        wp, gp, bp, mp, vp,
        (float*)d_out);
}